// round 3
// baseline (speedup 1.0000x reference)
#include <cuda_runtime.h>

#define N_NODES   100000
#define N_EDGES   1600000
#define NNZ       (N_EDGES + N_NODES)
#define IN_DIM    128
#define HID_DIM   128
#define OUT_DIM   64
#define NUM_GRAPHS 64
#define SCAN_BLOCK 1024
#define SCAN_NBLOCKS ((N_NODES + SCAN_BLOCK - 1) / SCAN_BLOCK)   // 98

// ---------------- scratch (static device globals; no allocs) ----------------
__device__ int   g_cnt[N_NODES];
__device__ int   g_counts[N_NODES];
__device__ int   g_offsets[N_NODES];
__device__ int   g_cursor[N_NODES];
__device__ float g_dinv[N_NODES];
__device__ int   g_blocksums[SCAN_NBLOCKS];
__device__ int   g_csr_src[NNZ];
__device__ float g_csr_norm[NNZ];
__device__ __align__(16) float g_h1[(size_t)N_NODES * HID_DIM];
__device__ __align__(16) float g_y1[(size_t)N_NODES * HID_DIM];
__device__ __align__(16) float g_h2[(size_t)N_NODES * OUT_DIM];
__device__ float g_pool[NUM_GRAPHS * OUT_DIM];
__device__ float g_pcnt[NUM_GRAPHS];

// ---------------- preprocessing ----------------
__global__ void k_zero() {
    int i = blockIdx.x * blockDim.x + threadIdx.x;
    if (i < N_NODES) g_cnt[i] = 0;
    if (i < NUM_GRAPHS * OUT_DIM) g_pool[i] = 0.f;
    if (i < NUM_GRAPHS) g_pcnt[i] = 0.f;
}

__global__ void k_deg(const int* __restrict__ dst) {
    int e = blockIdx.x * blockDim.x + threadIdx.x;
    if (e < N_EDGES) atomicAdd(&g_cnt[dst[e]], 1);
}

__global__ void k_dinv() {
    int i = blockIdx.x * blockDim.x + threadIdx.x;
    if (i < N_NODES) {
        int c = g_cnt[i] + 1;               // + self loop
        g_counts[i] = c;
        g_dinv[i] = rsqrtf((float)c);
    }
}

__global__ void k_scanA() {
    __shared__ int sm[SCAN_BLOCK];
    int i = blockIdx.x * SCAN_BLOCK + threadIdx.x;
    int v = (i < N_NODES) ? g_counts[i] : 0;
    sm[threadIdx.x] = v;
    __syncthreads();
    for (int d = 1; d < SCAN_BLOCK; d <<= 1) {
        int t = 0;
        if ((int)threadIdx.x >= d) t = sm[threadIdx.x - d];
        __syncthreads();
        if ((int)threadIdx.x >= d) sm[threadIdx.x] += t;
        __syncthreads();
    }
    if (i < N_NODES) g_offsets[i] = sm[threadIdx.x] - v;   // exclusive
    if (threadIdx.x == SCAN_BLOCK - 1) g_blocksums[blockIdx.x] = sm[SCAN_BLOCK - 1];
}

__global__ void k_scanB() {
    if (threadIdx.x == 0) {
        int run = 0;
        for (int b = 0; b < SCAN_NBLOCKS; b++) {
            int t = g_blocksums[b];
            g_blocksums[b] = run;
            run += t;
        }
    }
}

__global__ void k_scanC() {
    int i = blockIdx.x * SCAN_BLOCK + threadIdx.x;
    if (i < N_NODES) {
        int o = g_offsets[i] + g_blocksums[blockIdx.x];
        g_offsets[i] = o;
        g_cursor[i] = o;
    }
}

__global__ void k_scatter(const int* __restrict__ src,
                          const int* __restrict__ dst) {
    int i = blockIdx.x * blockDim.x + threadIdx.x;
    if (i >= NNZ) return;
    int s, d;
    if (i < N_EDGES) { s = src[i]; d = dst[i]; }
    else             { s = d = i - N_EDGES; }
    int pos = atomicAdd(&g_cursor[d], 1);
    g_csr_src[pos]  = s;
    g_csr_norm[pos] = g_dinv[s] * g_dinv[d];
}

// ---------------- dense GEMM body: C[M,BN] = A[M,K] @ B[K,BN] ----------------
template <int BN, int TN, int K>
__device__ __forceinline__ void sgemm_body(const float* __restrict__ A,
                                           const float* __restrict__ B,
                                           float* __restrict__ C, int M) {
    constexpr int BM = 128, BK = 8, TM = 8;
    constexpr int CGROUPS = BN / TN;   // 16
    __shared__ float As[BK][BM];
    __shared__ float Bs[BK][BN];
    int tid = threadIdx.x;             // 256 threads
    int tx = tid % CGROUPS;
    int ty = tid / CGROUPS;
    int row0 = blockIdx.x * BM;
    float acc[TM][TN];
#pragma unroll
    for (int i = 0; i < TM; i++)
#pragma unroll
        for (int j = 0; j < TN; j++) acc[i][j] = 0.f;

    for (int k0 = 0; k0 < K; k0 += BK) {
#pragma unroll
        for (int i = tid; i < BM * BK; i += 256) {
            int r = i / BK, c = i % BK;
            int gr = row0 + r;
            As[c][r] = (gr < M) ? A[(size_t)gr * K + k0 + c] : 0.f;
        }
#pragma unroll
        for (int i = tid; i < BK * BN; i += 256) {
            int r = i / BN, c = i % BN;
            Bs[r][c] = B[(size_t)(k0 + r) * BN + c];
        }
        __syncthreads();
#pragma unroll
        for (int kk = 0; kk < BK; kk++) {
            float a[TM], b[TN];
#pragma unroll
            for (int i = 0; i < TM; i++) a[i] = As[kk][ty * TM + i];
#pragma unroll
            for (int j = 0; j < TN; j++) b[j] = Bs[kk][tx * TN + j];
#pragma unroll
            for (int i = 0; i < TM; i++)
#pragma unroll
                for (int j = 0; j < TN; j++) acc[i][j] += a[i] * b[j];
        }
        __syncthreads();
    }
#pragma unroll
    for (int i = 0; i < TM; i++) {
        int gr = row0 + ty * TM + i;
        if (gr < M) {
#pragma unroll
            for (int j = 0; j < TN; j++)
                C[(size_t)gr * BN + tx * TN + j] = acc[i][j];
        }
    }
}

// wrappers bound to device-global outputs
__global__ void k_sgemm1(const float* __restrict__ A, const float* __restrict__ B) {
    sgemm_body<128, 8, IN_DIM>(A, B, g_h1, N_NODES);
}
__global__ void k_sgemm2(const float* __restrict__ B) {
    sgemm_body<64, 4, HID_DIM>(g_y1, B, g_h2, N_NODES);
}

// ---------------- CSR aggregation, D=128: y = relu(sum_j w_j * h[src_j] + b) ----------------
__global__ void k_agg_relu_128(const float* __restrict__ bias) {
    int warp = (blockIdx.x * blockDim.x + threadIdx.x) >> 5;
    if (warp >= N_NODES) return;
    int lane = threadIdx.x & 31;
    int off = g_offsets[warp];
    int cnt = g_counts[warp];
    const float* __restrict__ h = g_h1;
    float ax = 0.f, ay = 0.f, az = 0.f, aw = 0.f;
    int j = 0;
    for (; j + 2 <= cnt; j += 2) {
        int   s0 = g_csr_src[off + j];
        float w0 = g_csr_norm[off + j];
        int   s1 = g_csr_src[off + j + 1];
        float w1 = g_csr_norm[off + j + 1];
        float4 v0 = *reinterpret_cast<const float4*>(h + (size_t)s0 * 128 + lane * 4);
        float4 v1 = *reinterpret_cast<const float4*>(h + (size_t)s1 * 128 + lane * 4);
        ax += w0 * v0.x + w1 * v1.x;
        ay += w0 * v0.y + w1 * v1.y;
        az += w0 * v0.z + w1 * v1.z;
        aw += w0 * v0.w + w1 * v1.w;
    }
    if (j < cnt) {
        int   s0 = g_csr_src[off + j];
        float w0 = g_csr_norm[off + j];
        float4 v0 = *reinterpret_cast<const float4*>(h + (size_t)s0 * 128 + lane * 4);
        ax += w0 * v0.x; ay += w0 * v0.y; az += w0 * v0.z; aw += w0 * v0.w;
    }
    float4 b = *reinterpret_cast<const float4*>(bias + lane * 4);
    float4 r;
    r.x = fmaxf(ax + b.x, 0.f);
    r.y = fmaxf(ay + b.y, 0.f);
    r.z = fmaxf(az + b.z, 0.f);
    r.w = fmaxf(aw + b.w, 0.f);
    *reinterpret_cast<float4*>(g_y1 + (size_t)warp * 128 + lane * 4) = r;
}

// ---------------- CSR aggregation D=64 fused with bias+relu+mean-pool atomics ----------------
__global__ void k_agg_pool_64(const float* __restrict__ bias,
                              const int* __restrict__ batch) {
    int warp = (blockIdx.x * blockDim.x + threadIdx.x) >> 5;
    if (warp >= N_NODES) return;
    int lane = threadIdx.x & 31;
    int off = g_offsets[warp];
    int cnt = g_counts[warp];
    const float* __restrict__ h = g_h2;
    float a0 = 0.f, a1 = 0.f;
    int j = 0;
    for (; j + 2 <= cnt; j += 2) {
        int   s0 = g_csr_src[off + j];
        float w0 = g_csr_norm[off + j];
        int   s1 = g_csr_src[off + j + 1];
        float w1 = g_csr_norm[off + j + 1];
        float2 v0 = *reinterpret_cast<const float2*>(h + (size_t)s0 * 64 + lane * 2);
        float2 v1 = *reinterpret_cast<const float2*>(h + (size_t)s1 * 64 + lane * 2);
        a0 += w0 * v0.x + w1 * v1.x;
        a1 += w0 * v0.y + w1 * v1.y;
    }
    if (j < cnt) {
        int   s0 = g_csr_src[off + j];
        float w0 = g_csr_norm[off + j];
        float2 v0 = *reinterpret_cast<const float2*>(h + (size_t)s0 * 64 + lane * 2);
        a0 += w0 * v0.x;
        a1 += w0 * v0.y;
    }
    float r0 = fmaxf(a0 + bias[lane * 2], 0.f);
    float r1 = fmaxf(a1 + bias[lane * 2 + 1], 0.f);
    int g = batch[warp];
    atomicAdd(&g_pool[g * OUT_DIM + lane * 2], r0);
    atomicAdd(&g_pool[g * OUT_DIM + lane * 2 + 1], r1);
    if (lane == 0) atomicAdd(&g_pcnt[g], 1.f);
}

__global__ void k_finalize(float* __restrict__ out) {
    int i = blockIdx.x * blockDim.x + threadIdx.x;
    if (i < NUM_GRAPHS * OUT_DIM) {
        float c = g_pcnt[i >> 6];
        out[i] = g_pool[i] / fmaxf(c, 1.f);
    }
}

// ---------------- launch ----------------
extern "C" void kernel_launch(void* const* d_in, const int* in_sizes, int n_in,
                              void* d_out, int out_size) {
    const float* x     = (const float*)d_in[0];
    const int*   ei    = (const int*)d_in[1];      // int32! (JAX x64 disabled)
    const int*   batch = (const int*)d_in[2];      // int32!
    const float* W1    = (const float*)d_in[3];
    const float* b1    = (const float*)d_in[4];
    const float* W2    = (const float*)d_in[5];
    const float* b2    = (const float*)d_in[6];
    float*       out   = (float*)d_out;

    const int* src = ei;
    const int* dst = ei + N_EDGES;

    k_zero<<<(N_NODES + 255) / 256, 256>>>();
    k_deg<<<(N_EDGES + 255) / 256, 256>>>(dst);
    k_dinv<<<(N_NODES + 255) / 256, 256>>>();
    k_scanA<<<SCAN_NBLOCKS, SCAN_BLOCK>>>();
    k_scanB<<<1, 32>>>();
    k_scanC<<<SCAN_NBLOCKS, SCAN_BLOCK>>>();
    k_scatter<<<(NNZ + 255) / 256, 256>>>(src, dst);

    // layer 1: h1 = x @ W1 ; y1 = relu(agg(h1) + b1)
    k_sgemm1<<<(N_NODES + 127) / 128, 256>>>(x, W1);
    k_agg_relu_128<<<(N_NODES * 32 + 255) / 256, 256>>>(b1);

    // layer 2: h2 = y1 @ W2 ; pooled relu(agg(h2) + b2)
    k_sgemm2<<<(N_NODES + 127) / 128, 256>>>(W2);
    k_agg_pool_64<<<(N_NODES * 32 + 255) / 256, 256>>>(b2, batch);

    k_finalize<<<(NUM_GRAPHS * OUT_DIM + 255) / 256, 256>>>(out);
}

// round 5
// speedup vs baseline: 1.5458x; 1.5458x over previous
#include <cuda_runtime.h>
#include <cuda_bf16.h>

#define N_NODES   100000
#define N_EDGES   1600000
#define NNZ       (N_EDGES + N_NODES)
#define IN_DIM    128
#define HID_DIM   128
#define OUT_DIM   64
#define NUM_GRAPHS 64
#define SCAN_BLOCK 1024
#define SCAN_NBLOCKS ((N_NODES + SCAN_BLOCK - 1) / SCAN_BLOCK)   // 98

// ---------------- scratch (static device globals; no allocs) ----------------
__device__ int   g_cnt[N_NODES];
__device__ int   g_counts[N_NODES];
__device__ int   g_offsets[N_NODES];
__device__ int   g_cursor[N_NODES];
__device__ float g_dinv[N_NODES];
__device__ int   g_blocksums[SCAN_NBLOCKS];
__device__ __align__(16) int2 g_csr[NNZ];                     // {src, norm bits}
__device__ __align__(16) __nv_bfloat162 g_h1[(size_t)N_NODES * (HID_DIM / 2)];
__device__ __align__(16) __nv_bfloat162 g_y1[(size_t)N_NODES * (HID_DIM / 2)];
__device__ __align__(16) __nv_bfloat162 g_h2[(size_t)N_NODES * (OUT_DIM / 2)];
__device__ float g_pool[NUM_GRAPHS * OUT_DIM];
__device__ float g_pcnt[NUM_GRAPHS];

// ---------------- preprocessing ----------------
__global__ void k_zero() {
    int i = blockIdx.x * blockDim.x + threadIdx.x;
    if (i < N_NODES) g_cnt[i] = 0;
    if (i < NUM_GRAPHS * OUT_DIM) g_pool[i] = 0.f;
    if (i < NUM_GRAPHS) g_pcnt[i] = 0.f;
}

__global__ void k_deg(const int* __restrict__ dst) {
    int e = blockIdx.x * blockDim.x + threadIdx.x;
    if (e < N_EDGES) atomicAdd(&g_cnt[dst[e]], 1);
}

__global__ void k_dinv() {
    int i = blockIdx.x * blockDim.x + threadIdx.x;
    if (i < N_NODES) {
        int c = g_cnt[i] + 1;               // + self loop
        g_counts[i] = c;
        g_dinv[i] = rsqrtf((float)c);
    }
}

__global__ void k_scanA() {
    __shared__ int sm[SCAN_BLOCK];
    int i = blockIdx.x * SCAN_BLOCK + threadIdx.x;
    int v = (i < N_NODES) ? g_counts[i] : 0;
    sm[threadIdx.x] = v;
    __syncthreads();
    for (int d = 1; d < SCAN_BLOCK; d <<= 1) {
        int t = 0;
        if ((int)threadIdx.x >= d) t = sm[threadIdx.x - d];
        __syncthreads();
        if ((int)threadIdx.x >= d) sm[threadIdx.x] += t;
        __syncthreads();
    }
    if (i < N_NODES) g_offsets[i] = sm[threadIdx.x] - v;   // exclusive
    if (threadIdx.x == SCAN_BLOCK - 1) g_blocksums[blockIdx.x] = sm[SCAN_BLOCK - 1];
}

__global__ void k_scanB() {
    if (threadIdx.x == 0) {
        int run = 0;
        for (int b = 0; b < SCAN_NBLOCKS; b++) {
            int t = g_blocksums[b];
            g_blocksums[b] = run;
            run += t;
        }
    }
}

__global__ void k_scanC() {
    int i = blockIdx.x * SCAN_BLOCK + threadIdx.x;
    if (i < N_NODES) {
        int o = g_offsets[i] + g_blocksums[blockIdx.x];
        g_offsets[i] = o;
        g_cursor[i] = o;
    }
}

__global__ void k_scatter(const int* __restrict__ src,
                          const int* __restrict__ dst) {
    int i = blockIdx.x * blockDim.x + threadIdx.x;
    if (i >= NNZ) return;
    int s, d;
    if (i < N_EDGES) { s = src[i]; d = dst[i]; }
    else             { s = d = i - N_EDGES; }
    int pos = atomicAdd(&g_cursor[d], 1);
    g_csr[pos] = make_int2(s, __float_as_int(g_dinv[s] * g_dinv[d]));
}

// ---------------- dense GEMM body: C[M,BN] = A[M,K] @ B[K,BN], bf16 out ----------------
__device__ __forceinline__ float loadA(const float* p) { return *p; }
__device__ __forceinline__ float loadA(const __nv_bfloat16* p) { return __bfloat162float(*p); }

template <int BN, int TN, int K, typename TA>
__device__ __forceinline__ void sgemm_body(const TA* __restrict__ A,
                                           const float* __restrict__ B,
                                           __nv_bfloat162* __restrict__ C, int M) {
    constexpr int BM = 128, BK = 8, TM = 8;
    constexpr int CGROUPS = BN / TN;   // 16
    __shared__ float As[BK][BM];
    __shared__ float Bs[BK][BN];
    int tid = threadIdx.x;             // 256 threads
    int tx = tid % CGROUPS;
    int ty = tid / CGROUPS;
    int row0 = blockIdx.x * BM;
    float acc[TM][TN];
#pragma unroll
    for (int i = 0; i < TM; i++)
#pragma unroll
        for (int j = 0; j < TN; j++) acc[i][j] = 0.f;

    for (int k0 = 0; k0 < K; k0 += BK) {
#pragma unroll
        for (int i = tid; i < BM * BK; i += 256) {
            int r = i / BK, c = i % BK;
            int gr = row0 + r;
            As[c][r] = (gr < M) ? loadA(A + (size_t)gr * K + k0 + c) : 0.f;
        }
#pragma unroll
        for (int i = tid; i < BK * BN; i += 256) {
            int r = i / BN, c = i % BN;
            Bs[r][c] = B[(size_t)(k0 + r) * BN + c];
        }
        __syncthreads();
#pragma unroll
        for (int kk = 0; kk < BK; kk++) {
            float a[TM], b[TN];
#pragma unroll
            for (int i = 0; i < TM; i++) a[i] = As[kk][ty * TM + i];
#pragma unroll
            for (int j = 0; j < TN; j++) b[j] = Bs[kk][tx * TN + j];
#pragma unroll
            for (int i = 0; i < TM; i++)
#pragma unroll
                for (int j = 0; j < TN; j++) acc[i][j] += a[i] * b[j];
        }
        __syncthreads();
    }
#pragma unroll
    for (int i = 0; i < TM; i++) {
        int gr = row0 + ty * TM + i;
        if (gr < M) {
            __nv_bfloat162 tmp[TN / 2];
#pragma unroll
            for (int j = 0; j < TN; j += 2) {
                float2 p = make_float2(acc[i][j], acc[i][j + 1]);
                tmp[j / 2] = __float22bfloat162_rn(p);
            }
            __nv_bfloat162* cp = C + (size_t)gr * (BN / 2) + tx * (TN / 2);
            if constexpr (TN == 8) {
                *reinterpret_cast<uint4*>(cp) = *reinterpret_cast<uint4*>(tmp);
            } else {
                *reinterpret_cast<uint2*>(cp) = *reinterpret_cast<uint2*>(tmp);
            }
        }
    }
}

__global__ void k_sgemm1(const float* __restrict__ A, const float* __restrict__ B) {
    sgemm_body<128, 8, IN_DIM>(A, B, g_h1, N_NODES);
}
__global__ void k_sgemm2(const float* __restrict__ B) {
    sgemm_body<64, 4, HID_DIM>(reinterpret_cast<const __nv_bfloat16*>(g_y1), B, g_h2, N_NODES);
}

// ---------------- CSR aggregation, D=128 (bf16 in/out), warp per node ----------------
__global__ void k_agg_relu_128(const float* __restrict__ bias) {
    int warp = (blockIdx.x * blockDim.x + threadIdx.x) >> 5;   // exact: 100000 warps
    int lane = threadIdx.x & 31;
    int j   = g_offsets[warp];
    int end = j + g_counts[warp];
    const int2* __restrict__ csr = g_csr;
    const uint2* __restrict__ h = reinterpret_cast<const uint2*>(g_h1);  // 4 cols / elem
    float ax = 0.f, ay = 0.f, az = 0.f, aw = 0.f;

#define AGG128_ONE(E, U)                                                  \
    {                                                                     \
        float w = __int_as_float((E).y);                                  \
        __nv_bfloat162 p0 = *reinterpret_cast<__nv_bfloat162*>(&(U).x);   \
        __nv_bfloat162 p1 = *reinterpret_cast<__nv_bfloat162*>(&(U).y);   \
        float2 f0 = __bfloat1622float2(p0);                               \
        float2 f1 = __bfloat1622float2(p1);                               \
        ax += w * f0.x; ay += w * f0.y; az += w * f1.x; aw += w * f1.y;   \
    }

    for (; j + 4 <= end; j += 4) {
        int2 e0 = csr[j], e1 = csr[j + 1], e2 = csr[j + 2], e3 = csr[j + 3];
        uint2 u0 = h[(size_t)e0.x * 32 + lane];
        uint2 u1 = h[(size_t)e1.x * 32 + lane];
        uint2 u2 = h[(size_t)e2.x * 32 + lane];
        uint2 u3 = h[(size_t)e3.x * 32 + lane];
        AGG128_ONE(e0, u0) AGG128_ONE(e1, u1) AGG128_ONE(e2, u2) AGG128_ONE(e3, u3)
    }
    for (; j < end; j++) {
        int2 e0 = csr[j];
        uint2 u0 = h[(size_t)e0.x * 32 + lane];
        AGG128_ONE(e0, u0)
    }
#undef AGG128_ONE

    float4 b = reinterpret_cast<const float4*>(bias)[lane];
    __nv_bfloat162 o[2];
    o[0] = __float22bfloat162_rn(make_float2(fmaxf(ax + b.x, 0.f), fmaxf(ay + b.y, 0.f)));
    o[1] = __float22bfloat162_rn(make_float2(fmaxf(az + b.z, 0.f), fmaxf(aw + b.w, 0.f)));
    uint2* out = reinterpret_cast<uint2*>(g_y1);
    out[(size_t)warp * 32 + lane] = *reinterpret_cast<uint2*>(o);
}

// ---------------- CSR aggregation D=64 (bf16 in) + bias/relu + pooled mean ----------------
__global__ void k_agg_pool_64(const float* __restrict__ bias,
                              const int* __restrict__ batch) {
    int warpId = threadIdx.x >> 5;
    int node = blockIdx.x * 8 + warpId;                        // exact: 12500*8
    int lane = threadIdx.x & 31;
    int j   = g_offsets[node];
    int end = j + g_counts[node];
    const int2* __restrict__ csr = g_csr;
    const __nv_bfloat162* __restrict__ h = g_h2;               // 2 cols / elem
    float a0 = 0.f, a1 = 0.f;

#define AGG64_ONE(E, P)                                        \
    {                                                          \
        float w = __int_as_float((E).y);                       \
        float2 f = __bfloat1622float2(P);                      \
        a0 += w * f.x; a1 += w * f.y;                          \
    }

    for (; j + 4 <= end; j += 4) {
        int2 e0 = csr[j], e1 = csr[j + 1], e2 = csr[j + 2], e3 = csr[j + 3];
        __nv_bfloat162 p0 = h[(size_t)e0.x * 32 + lane];
        __nv_bfloat162 p1 = h[(size_t)e1.x * 32 + lane];
        __nv_bfloat162 p2 = h[(size_t)e2.x * 32 + lane];
        __nv_bfloat162 p3 = h[(size_t)e3.x * 32 + lane];
        AGG64_ONE(e0, p0) AGG64_ONE(e1, p1) AGG64_ONE(e2, p2) AGG64_ONE(e3, p3)
    }
    for (; j < end; j++) {
        int2 e0 = csr[j];
        __nv_bfloat162 p0 = h[(size_t)e0.x * 32 + lane];
        AGG64_ONE(e0, p0)
    }
#undef AGG64_ONE

    float2 b = reinterpret_cast<const float2*>(bias)[lane];
    float r0 = fmaxf(a0 + b.x, 0.f);
    float r1 = fmaxf(a1 + b.y, 0.f);
    int g = batch[node];

    __shared__ int   sg[8];
    __shared__ float sp[OUT_DIM];
    if (threadIdx.x < OUT_DIM) sp[threadIdx.x] = 0.f;
    if (lane == 0) sg[warpId] = g;
    __syncthreads();
    bool uni = true;
#pragma unroll
    for (int k = 1; k < 8; k++) uni &= (sg[k] == sg[0]);

    if (uni) {
        atomicAdd(&sp[lane * 2], r0);
        atomicAdd(&sp[lane * 2 + 1], r1);
        __syncthreads();
        if (threadIdx.x < OUT_DIM)
            atomicAdd(&g_pool[sg[0] * OUT_DIM + threadIdx.x], sp[threadIdx.x]);
        if (threadIdx.x == 0) atomicAdd(&g_pcnt[sg[0]], 8.f);
    } else {
        atomicAdd(&g_pool[g * OUT_DIM + lane * 2], r0);
        atomicAdd(&g_pool[g * OUT_DIM + lane * 2 + 1], r1);
        if (lane == 0) atomicAdd(&g_pcnt[g], 1.f);
    }
}

__global__ void k_finalize(float* __restrict__ out) {
    int i = blockIdx.x * blockDim.x + threadIdx.x;
    if (i < NUM_GRAPHS * OUT_DIM) {
        float c = g_pcnt[i >> 6];
        out[i] = g_pool[i] / fmaxf(c, 1.f);
    }
}

// ---------------- launch ----------------
extern "C" void kernel_launch(void* const* d_in, const int* in_sizes, int n_in,
                              void* d_out, int out_size) {
    const float* x     = (const float*)d_in[0];
    const int*   ei    = (const int*)d_in[1];      // int32 (JAX x64 disabled)
    const int*   batch = (const int*)d_in[2];      // int32
    const float* W1    = (const float*)d_in[3];
    const float* b1    = (const float*)d_in[4];
    const float* W2    = (const float*)d_in[5];
    const float* b2    = (const float*)d_in[6];
    float*       out   = (float*)d_out;

    const int* src = ei;
    const int* dst = ei + N_EDGES;

    k_zero<<<(N_NODES + 255) / 256, 256>>>();
    k_deg<<<(N_EDGES + 255) / 256, 256>>>(dst);
    k_dinv<<<(N_NODES + 255) / 256, 256>>>();
    k_scanA<<<SCAN_NBLOCKS, SCAN_BLOCK>>>();
    k_scanB<<<1, 32>>>();
    k_scanC<<<SCAN_NBLOCKS, SCAN_BLOCK>>>();
    k_scatter<<<(NNZ + 255) / 256, 256>>>(src, dst);

    // layer 1: h1 = x @ W1 (bf16 out) ; y1 = relu(agg(h1) + b1) (bf16)
    k_sgemm1<<<(N_NODES + 127) / 128, 256>>>(x, W1);
    k_agg_relu_128<<<N_NODES / 8, 256>>>(b1);

    // layer 2: h2 = y1 @ W2 (bf16 out) ; pooled relu(agg(h2) + b2)
    k_sgemm2<<<(N_NODES + 127) / 128, 256>>>(W2);
    k_agg_pool_64<<<N_NODES / 8, 256>>>(b2, batch);

    k_finalize<<<(NUM_GRAPHS * OUT_DIM + 255) / 256, 256>>>(out);
}